// round 1
// baseline (speedup 1.0000x reference)
#include <cuda_runtime.h>
#include <math.h>

#define BQ      1024      // query batch
#define D_IN    96
#define D_MAIN  512
#define D_BLOCK 1024
#define N_CAND  65536
#define N_CLS   10

// ---------------- scratch (static device globals; no allocation) ----------------
__device__ float g_ctxvals[(size_t)N_CAND * D_MAIN];   // 128 MB
__device__ float g_logits [(size_t)BQ * N_CAND];       // 256 MB (reused as exp-weights)
__device__ float g_qa     [BQ * D_MAIN];
__device__ float g_qb     [BQ * D_MAIN];
__device__ float g_h      [BQ * D_BLOCK];
__device__ float g_ctx    [BQ * D_MAIN];
__device__ float g_rowsum [BQ];

// ---------------- generic 128x128x8 SGEMM, 256 thr, 8x8 microtile ----------------
// A: row-major [M,K].  B: NN -> row-major [K,N]; NT (BT=true) -> row-major [N,K].
// Requires: M,N multiples of 128; K (and split chunk) multiples of 8. All true here.
template<bool BT, bool BIAS, bool RELU, bool SPLITK>
__global__ void __launch_bounds__(256) sgemm128(
    const float* __restrict__ A, const float* __restrict__ B,
    const float* __restrict__ bias, float* __restrict__ C,
    int M, int N, int K, float alpha, int kChunk)
{
    __shared__ float As[8][128];
    __shared__ float Bs[8][128];
    const int t  = threadIdx.x;
    const int m0 = blockIdx.y * 128;
    const int n0 = blockIdx.x * 128;

    int kStart = 0, kEnd = K;
    if (SPLITK) { kStart = blockIdx.z * kChunk; kEnd = min(K, kStart + kChunk); }

    const int arow = t >> 1;            // 0..127
    const int aseg = (t & 1) * 4;       // 0 or 4
    const int brow = t >> 5;            // 0..7   (NN path)
    const int bcol = (t & 31) * 4;      // 0..124 (NN path)

    const int ty = (t >> 4) * 8;        // row offset in tile
    const int tx = (t & 15) * 8;        // col offset in tile

    float acc[8][8];
    #pragma unroll
    for (int i = 0; i < 8; ++i)
        #pragma unroll
        for (int j = 0; j < 8; ++j) acc[i][j] = 0.f;

    for (int kk = kStart; kk < kEnd; kk += 8) {
        // A tile -> As[k][m] (transposed store)
        float4 va = *(const float4*)(A + (size_t)(m0 + arow) * K + kk + aseg);
        As[aseg + 0][arow] = va.x; As[aseg + 1][arow] = va.y;
        As[aseg + 2][arow] = va.z; As[aseg + 3][arow] = va.w;

        if (BT) {
            // B row-major [N,K]: same pattern as A, transposed store -> Bs[k][n]
            float4 vb = *(const float4*)(B + (size_t)(n0 + arow) * K + kk + aseg);
            Bs[aseg + 0][arow] = vb.x; Bs[aseg + 1][arow] = vb.y;
            Bs[aseg + 2][arow] = vb.z; Bs[aseg + 3][arow] = vb.w;
        } else {
            // B row-major [K,N]: direct store -> Bs[k][n]
            float4 vb = *(const float4*)(B + (size_t)(kk + brow) * N + n0 + bcol);
            *(float4*)&Bs[brow][bcol] = vb;
        }
        __syncthreads();

        #pragma unroll
        for (int k = 0; k < 8; ++k) {
            float ar[8], br[8];
            #pragma unroll
            for (int i = 0; i < 8; ++i) ar[i] = As[k][ty + i];
            #pragma unroll
            for (int j = 0; j < 8; ++j) br[j] = Bs[k][tx + j];
            #pragma unroll
            for (int i = 0; i < 8; ++i)
                #pragma unroll
                for (int j = 0; j < 8; ++j)
                    acc[i][j] = fmaf(ar[i], br[j], acc[i][j]);
        }
        __syncthreads();
    }

    #pragma unroll
    for (int i = 0; i < 8; ++i) {
        const size_t crow = (size_t)(m0 + ty + i) * N;
        #pragma unroll
        for (int j = 0; j < 8; ++j) {
            const int n = n0 + tx + j;
            float v = acc[i][j] * alpha;
            if (BIAS) v += bias[n];
            if (RELU) v = fmaxf(v, 0.f);
            if (SPLITK) atomicAdd(&C[crow + n], v);
            else        C[crow + n] = v;
        }
    }
}

// ---------------- row softmax: store unnormalized exp + row sum ----------------
__global__ void __launch_bounds__(256) softmax_exp_kernel(
    float* __restrict__ logits, float* __restrict__ rowsum)
{
    const int b = blockIdx.x;
    float4* row = (float4*)(logits + (size_t)b * N_CAND);
    const int n4 = N_CAND / 4;
    __shared__ float red[256];

    float m = -1e30f;
    for (int i = threadIdx.x; i < n4; i += 256) {
        float4 v = row[i];
        m = fmaxf(m, fmaxf(fmaxf(v.x, v.y), fmaxf(v.z, v.w)));
    }
    red[threadIdx.x] = m; __syncthreads();
    for (int s = 128; s; s >>= 1) {
        if (threadIdx.x < s) red[threadIdx.x] = fmaxf(red[threadIdx.x], red[threadIdx.x + s]);
        __syncthreads();
    }
    const float rmax = red[0];
    __syncthreads();

    float sum = 0.f;
    for (int i = threadIdx.x; i < n4; i += 256) {
        float4 v = row[i];
        v.x = __expf(v.x - rmax); v.y = __expf(v.y - rmax);
        v.z = __expf(v.z - rmax); v.w = __expf(v.w - rmax);
        sum += v.x + v.y + v.z + v.w;
        row[i] = v;
    }
    red[threadIdx.x] = sum; __syncthreads();
    for (int s = 128; s; s >>= 1) {
        if (threadIdx.x < s) red[threadIdx.x] += red[threadIdx.x + s];
        __syncthreads();
    }
    if (threadIdx.x == 0) rowsum[b] = red[0];
}

// ---------------- zero-fill (for split-K atomic accumulation) ----------------
__global__ void zero_kernel(float* __restrict__ p, int n)
{
    int i = blockIdx.x * 256 + threadIdx.x;
    if (i < n) p[i] = 0.f;
}

// ---------------- head: out = (q + ctx/rowsum) @ head_w + head_b ----------------
// 1 block per query row, 10 warps (one per class)
__global__ void __launch_bounds__(320) head_kernel(
    const float* __restrict__ q, const float* __restrict__ ctx,
    const float* __restrict__ rowsum,
    const float* __restrict__ hw, const float* __restrict__ hb,
    float* __restrict__ out)
{
    const int b    = blockIdx.x;
    const int warp = threadIdx.x >> 5;
    const int lane = threadIdx.x & 31;
    if (warp >= N_CLS) return;

    const float inv = 1.f / rowsum[b];
    float s = 0.f;
    #pragma unroll 4
    for (int d = lane; d < D_MAIN; d += 32)
        s += (q[b * D_MAIN + d] + ctx[b * D_MAIN + d] * inv) * hw[d * N_CLS + warp];

    #pragma unroll
    for (int off = 16; off; off >>= 1)
        s += __shfl_down_sync(0xFFFFFFFFu, s, off);

    if (lane == 0) out[b * N_CLS + warp] = s + hb[warp];
}

// ---------------- launch ----------------
extern "C" void kernel_launch(void* const* d_in, const int* in_sizes, int n_in,
                              void* d_out, int out_size)
{
    const float* x    = (const float*)d_in[0];
    const float* cand = (const float*)d_in[1];
    const float* w0   = (const float*)d_in[2];
    const float* b0   = (const float*)d_in[3];
    const float* w1   = (const float*)d_in[4];   // [2, 512, 1024]
    const float* b1   = (const float*)d_in[5];   // [2, 1024]
    const float* w2   = (const float*)d_in[6];   // [2, 1024, 512]
    const float* b2   = (const float*)d_in[7];   // [2, 512]
    const float* tw   = (const float*)d_in[8];
    const float* tb   = (const float*)d_in[9];
    const float* hw   = (const float*)d_in[10];
    const float* hb   = (const float*)d_in[11];
    float* out = (float*)d_out;

    float *qa, *qb, *h, *ctxv, *logits, *ctx, *rowsum;
    cudaGetSymbolAddress((void**)&qa,     g_qa);
    cudaGetSymbolAddress((void**)&qb,     g_qb);
    cudaGetSymbolAddress((void**)&h,      g_h);
    cudaGetSymbolAddress((void**)&ctxv,   g_ctxvals);
    cudaGetSymbolAddress((void**)&logits, g_logits);
    cudaGetSymbolAddress((void**)&ctx,    g_ctx);
    cudaGetSymbolAddress((void**)&rowsum, g_rowsum);

    const dim3 blk(256);
    const float scale = (float)(1.0 / (sqrt(512.0) * 0.2));

    // ---- query encoder ----
    // q = x @ w0 + b0            [1024,512], K=96
    sgemm128<false, true, false, false><<<dim3(D_MAIN/128, BQ/128), blk>>>(
        x, w0, b0, qa, BQ, D_MAIN, D_IN, 1.f, 0);
    // block 0: h = relu(q @ w1[0] + b1[0]); q = h @ w2[0] + b2[0]
    sgemm128<false, true, true, false><<<dim3(D_BLOCK/128, BQ/128), blk>>>(
        qa, w1, b1, h, BQ, D_BLOCK, D_MAIN, 1.f, 0);
    sgemm128<false, true, false, false><<<dim3(D_MAIN/128, BQ/128), blk>>>(
        h, w2, b2, qb, BQ, D_MAIN, D_BLOCK, 1.f, 0);
    // block 1
    sgemm128<false, true, true, false><<<dim3(D_BLOCK/128, BQ/128), blk>>>(
        qb, w1 + (size_t)D_MAIN * D_BLOCK, b1 + D_BLOCK, h, BQ, D_BLOCK, D_MAIN, 1.f, 0);
    sgemm128<false, true, false, false><<<dim3(D_MAIN/128, BQ/128), blk>>>(
        h, w2 + (size_t)D_BLOCK * D_MAIN, b2 + D_MAIN, qa, BQ, D_MAIN, D_BLOCK, 1.f, 0);

    // ---- candidate transformation: ctx_vals = cand @ trans_w + trans_b ----
    sgemm128<false, true, false, false><<<dim3(D_MAIN/128, N_CAND/128), blk>>>(
        cand, tw, tb, ctxv, N_CAND, D_MAIN, D_MAIN, 1.f, 0);

    // ---- logits = scale * (q @ cand^T)   (NT) ----
    sgemm128<true, false, false, false><<<dim3(N_CAND/128, BQ/128), blk>>>(
        qa, cand, nullptr, logits, BQ, N_CAND, D_MAIN, scale, 0);

    // ---- softmax (unnormalized exp in-place + row sums) ----
    softmax_exp_kernel<<<BQ, 256>>>(logits, rowsum);

    // ---- context = exp_weights @ ctx_vals  (split-K=32, atomic accumulate) ----
    zero_kernel<<<(BQ * D_MAIN + 255) / 256, 256>>>(ctx, BQ * D_MAIN);
    sgemm128<false, false, false, true><<<dim3(D_MAIN/128, BQ/128, 32), blk>>>(
        logits, ctxv, nullptr, ctx, BQ, D_MAIN, N_CAND, 1.f, N_CAND / 32);

    // ---- head: out = (q + context/rowsum) @ head_w + head_b ----
    head_kernel<<<BQ, 320>>>(qa, ctx, rowsum, hw, hb, out);
}